// round 3
// baseline (speedup 1.0000x reference)
#include <cuda_runtime.h>
#include <math.h>

#define B_   2
#define T_   2048
#define C_   2048
#define H_   16
#define KVH_ 4
#define HD_  128
#define MROWS (B_*T_)   // 4096

// ---------------- scratch (device globals; no allocations) ----------------
__device__ float g_Q[B_*T_*H_*HD_];       // [b*T+t][h*128+d]   32MB
__device__ float g_K[B_*T_*KVH_*HD_];     // [b*T+s][kh*128+d]   8MB
__device__ float g_V[B_*T_*KVH_*HD_];     // [b*T+s][kh*128+d]   8MB
__device__ float g_Kt[B_*KVH_*HD_*T_];    // [((b*KVH+kh)*128+d)*T + s]  8MB
__device__ float g_O[B_*T_*H_*HD_];       // [b*T+t][h*128+d]   32MB

// =====================================================================
// Tiled fp32 GEMM:  C[M,N] = A[M,K] @ W[K,N] (+bias).  M = gridDim.y*128.
// 128x128 block, BK=16, 256 threads, 8x8 micro-tile (split cols 0..63/64..127)
// =====================================================================
__global__ void __launch_bounds__(256) gemm_kernel(
    const float* __restrict__ A, const float* __restrict__ W,
    const float* __restrict__ bias, float* __restrict__ Cout,
    int N, int K)
{
    __shared__ float As[16][132];   // transposed A tile: As[k][row]
    __shared__ float Bs[16][132];   // Bs[k][col]

    const int tid    = threadIdx.x;
    const int rowBlk = blockIdx.y * 128;
    const int colBlk = blockIdx.x * 128;
    const int cx     = tid & 15;
    const int ry     = tid >> 4;
    const int row0   = ry * 8;

    float acc[8][8];
#pragma unroll
    for (int i = 0; i < 8; i++)
#pragma unroll
        for (int j = 0; j < 8; j++) acc[i][j] = 0.f;

    const int ar = tid >> 2;            // 0..63
    const int ak = (tid & 3) * 4;       // 0,4,8,12
    const int bkr = tid >> 5;           // 0..7
    const int bc  = (tid & 31) * 4;     // 0..124

    for (int kb = 0; kb < K; kb += 16) {
#pragma unroll
        for (int it = 0; it < 2; it++) {
            int r = ar + it * 64;
            float4 v = *(const float4*)(A + (long)(rowBlk + r) * K + kb + ak);
            As[ak + 0][r] = v.x; As[ak + 1][r] = v.y;
            As[ak + 2][r] = v.z; As[ak + 3][r] = v.w;
        }
#pragma unroll
        for (int it = 0; it < 2; it++) {
            int k = bkr + it * 8;
            *(float4*)&Bs[k][bc] =
                *(const float4*)(W + (long)(kb + k) * N + colBlk + bc);
        }
        __syncthreads();
#pragma unroll
        for (int k = 0; k < 16; k++) {
            float a[8], b[8];
            *(float4*)&a[0] = *(float4*)&As[k][row0];
            *(float4*)&a[4] = *(float4*)&As[k][row0 + 4];
            *(float4*)&b[0] = *(float4*)&Bs[k][cx * 4];
            *(float4*)&b[4] = *(float4*)&Bs[k][64 + cx * 4];
#pragma unroll
            for (int i = 0; i < 8; i++)
#pragma unroll
                for (int j = 0; j < 8; j++)
                    acc[i][j] = fmaf(a[i], b[j], acc[i][j]);
        }
        __syncthreads();
    }

    float4 b0 = make_float4(0.f,0.f,0.f,0.f), b1 = b0;
    if (bias) {
        b0 = *(const float4*)(bias + colBlk + cx*4);
        b1 = *(const float4*)(bias + colBlk + 64 + cx*4);
    }
#pragma unroll
    for (int i = 0; i < 8; i++) {
        float* cp = Cout + (long)(rowBlk + row0 + i) * N + colBlk;
        *(float4*)(cp + cx*4) =
            make_float4(acc[i][0]+b0.x, acc[i][1]+b0.y, acc[i][2]+b0.z, acc[i][3]+b0.w);
        *(float4*)(cp + 64 + cx*4) =
            make_float4(acc[i][4]+b1.x, acc[i][5]+b1.y, acc[i][6]+b1.z, acc[i][7]+b1.w);
    }
}

// =====================================================================
// RoPE on Q, in place. One thread per (b,t,h,d<64) pair -> race-free.
// =====================================================================
__global__ void __launch_bounds__(256) rope_q_kernel()
{
    int idx = blockIdx.x * 256 + threadIdx.x;   // over B*T*H*64
    int d  = idx & 63;
    int rh = idx >> 6;          // bt*H + h
    int h  = rh & (H_ - 1);
    int bt = rh >> 4;
    int t  = bt & (T_ - 1);
    long base = (long)bt * (H_*HD_) + h * HD_;
    // inv_freq = theta^(-d/64), ln(10000) = 9.210340371976184
    float invf = expf(-(float)d * (9.210340371976184f / 64.0f));
    float sn, cs;
    sincosf((float)t * invf, &sn, &cs);
    float x1 = g_Q[base + d];
    float x2 = g_Q[base + d + 64];
    g_Q[base + d]      = x1 * cs - x2 * sn;
    g_Q[base + d + 64] = x2 * cs + x1 * sn;
}

// =====================================================================
// RoPE on K + transpose to [B,KVH,HD,T] via 32x32 smem tiles.
// grid: (T/32, 2, B*KVH), block 256.
// =====================================================================
__global__ void __launch_bounds__(256) ropeT_k_kernel()
{
    __shared__ float sm1[32][33];
    __shared__ float sm2[32][33];
    const int tid = threadIdx.x;
    const int s0  = blockIdx.x * 32;
    const int d0  = blockIdx.y * 32;      // 0 or 32 (freq-index block)
    const int bkh = blockIdx.z;           // b*KVH + kh
    const int b   = bkh >> 2;
    const int kh  = bkh & 3;

    // load two 32x32 tiles: cols [d0, d0+32) and [d0+64, d0+96)
    {
        int r  = tid >> 3;
        int c4 = (tid & 7) * 4;
        long gbase = (long)(b*T_ + s0 + r) * (KVH_*HD_) + kh * HD_;
        float4 v1 = *(const float4*)(g_K + gbase + d0 + c4);
        float4 v2 = *(const float4*)(g_K + gbase + d0 + 64 + c4);
        sm1[r][c4+0]=v1.x; sm1[r][c4+1]=v1.y; sm1[r][c4+2]=v1.z; sm1[r][c4+3]=v1.w;
        sm2[r][c4+0]=v2.x; sm2[r][c4+1]=v2.y; sm2[r][c4+2]=v2.z; sm2[r][c4+3]=v2.w;
    }
    __syncthreads();

    const int dl = tid >> 2;     // 0..63  (first 32 -> low half, rest -> high half)
    const int cg = tid & 3;
    const int dd = dl & 31;
    float invf = expf(-(float)(d0 + dd) * (9.210340371976184f / 64.0f));
    int dglob = (dl < 32) ? (d0 + dd) : (64 + d0 + dd);
    long obase = (long)(bkh * HD_ + dglob) * T_;
#pragma unroll
    for (int i = 0; i < 8; i++) {
        int cc = cg * 8 + i;
        int t  = s0 + cc;
        float sn, cs;
        sincosf((float)t * invf, &sn, &cs);
        float x1 = sm1[cc][dd];
        float x2 = sm2[cc][dd];
        float out = (dl < 32) ? (x1 * cs - x2 * sn) : (x2 * cs + x1 * sn);
        g_Kt[obase + t] = out;
    }
}

// =====================================================================
// Flash attention (causal, GQA). BM=BN=64, 256 threads, fp32 online softmax.
// grid: (T/64, H, B). dynamic smem = 115200 B.
// =====================================================================
__global__ void __launch_bounds__(256, 2) flash_kernel()
{
    extern __shared__ float sm[];
    float* Qs       = sm;                  // [64][128]
    float* Kts      = Qs  + 64*128;        // [128][64]  (K^T tile)
    float* Vs       = Kts + 128*64;        // [64][128]
    float* Psm      = Vs  + 64*128;        // [64][64]   row-major P
    float* alpha_sm = Psm + 64*64;         // [64]
    float* lsm      = alpha_sm + 64;       // [64]

    const int tid = threadIdx.x;
    const int qt  = blockIdx.x;
    const int h   = blockIdx.y;
    const int b   = blockIdx.z;
    const int kh  = h >> 2;                // GQA group 4
    const int t0  = qt * 64;

    // load Q tile
    {
        const float* qg = g_Q + (long)(b*T_ + t0) * (H_*HD_) + h*HD_;
#pragma unroll
        for (int it = 0; it < 8; it++) {
            int idx = tid + it*256;
            int r = idx >> 5, d4 = (idx & 31) * 4;
            *(float4*)&Qs[r*128 + d4] = *(const float4*)(qg + (long)r*(H_*HD_) + d4);
        }
    }

    const int sx = tid & 15, sy = tid >> 4;
    const int sr0 = sy*4,  sc0 = sx*4;       // S-phase 4x4 tile
    const int ocx = tid & 31, ory = tid >> 5;
    const int or0 = ory*8, oc0 = ocx*4;      // O-phase 8x4 tile

    float m_i[4], l_i[4];
#pragma unroll
    for (int i = 0; i < 4; i++) { m_i[i] = -1e30f; l_i[i] = 0.f; }
    float oacc[8][4];
#pragma unroll
    for (int i = 0; i < 8; i++)
#pragma unroll
        for (int c = 0; c < 4; c++) oacc[i][c] = 0.f;

    const float* kg = g_Kt + (long)(b*KVH_ + kh) * HD_ * T_;
    const float* vg = g_V  + (long)b*T_*(KVH_*HD_) + kh*HD_;
    const float scale = 0.08838834764831845f;  // 1/sqrt(128)

    for (int kt = 0; kt <= qt; kt++) {
        const int s0 = kt * 64;
        __syncthreads();   // protect Kts/Vs from previous iteration's readers
        // load K^T tile [128][64] (coalesced from pre-transposed global)
#pragma unroll
        for (int it = 0; it < 8; it++) {
            int idx = tid + it*256;
            int d = idx >> 4, c4 = (idx & 15) * 4;
            *(float4*)&Kts[d*64 + c4] = *(const float4*)(kg + (long)d*T_ + s0 + c4);
        }
        // load V tile [64][128]
#pragma unroll
        for (int it = 0; it < 8; it++) {
            int idx = tid + it*256;
            int c = idx >> 5, d4 = (idx & 31) * 4;
            *(float4*)&Vs[c*128 + d4] = *(const float4*)(vg + (long)(s0 + c)*(KVH_*HD_) + d4);
        }
        __syncthreads();

        // ---- S = Q @ K^T (4x4 per thread) ----
        float s[4][4];
#pragma unroll
        for (int i = 0; i < 4; i++)
#pragma unroll
            for (int j = 0; j < 4; j++) s[i][j] = 0.f;

#pragma unroll 4
        for (int dq = 0; dq < 128; dq += 4) {
            float4 q0 = *(const float4*)&Qs[(sr0+0)*128 + dq];
            float4 q1 = *(const float4*)&Qs[(sr0+1)*128 + dq];
            float4 q2 = *(const float4*)&Qs[(sr0+2)*128 + dq];
            float4 q3 = *(const float4*)&Qs[(sr0+3)*128 + dq];
            float4 k0 = *(const float4*)&Kts[(dq+0)*64 + sc0];
            float4 k1 = *(const float4*)&Kts[(dq+1)*64 + sc0];
            float4 k2 = *(const float4*)&Kts[(dq+2)*64 + sc0];
            float4 k3 = *(const float4*)&Kts[(dq+3)*64 + sc0];
#define SROW(i, qv) \
            s[i][0] = fmaf(qv.x,k0.x, fmaf(qv.y,k1.x, fmaf(qv.z,k2.x, fmaf(qv.w,k3.x, s[i][0])))); \
            s[i][1] = fmaf(qv.x,k0.y, fmaf(qv.y,k1.y, fmaf(qv.z,k2.y, fmaf(qv.w,k3.y, s[i][1])))); \
            s[i][2] = fmaf(qv.x,k0.z, fmaf(qv.y,k1.z, fmaf(qv.z,k2.z, fmaf(qv.w,k3.z, s[i][2])))); \
            s[i][3] = fmaf(qv.x,k0.w, fmaf(qv.y,k1.w, fmaf(qv.z,k2.w, fmaf(qv.w,k3.w, s[i][3]))));
            SROW(0, q0) SROW(1, q1) SROW(2, q2) SROW(3, q3)
#undef SROW
        }

        // scale + causal mask (diagonal tile only)
        if (kt == qt) {
#pragma unroll
            for (int i = 0; i < 4; i++)
#pragma unroll
                for (int j = 0; j < 4; j++) {
                    s[i][j] *= scale;
                    if (s0 + sc0 + j > t0 + sr0 + i) s[i][j] = -1e30f;
                }
        } else {
#pragma unroll
            for (int i = 0; i < 4; i++)
#pragma unroll
                for (int j = 0; j < 4; j++) s[i][j] *= scale;
        }

        // row max over the 16 lanes sharing each row
        float mt[4];
#pragma unroll
        for (int i = 0; i < 4; i++)
            mt[i] = fmaxf(fmaxf(s[i][0], s[i][1]), fmaxf(s[i][2], s[i][3]));
#pragma unroll
        for (int off = 8; off > 0; off >>= 1)
#pragma unroll
            for (int i = 0; i < 4; i++)
                mt[i] = fmaxf(mt[i], __shfl_xor_sync(0xffffffffu, mt[i], off));

        float al[4], rs[4];
#pragma unroll
        for (int i = 0; i < 4; i++) {
            float mn = fmaxf(m_i[i], mt[i]);
            al[i] = __expf(m_i[i] - mn);
            m_i[i] = mn;
            float r = 0.f;
#pragma unroll
            for (int j = 0; j < 4; j++) {
                float p = __expf(s[i][j] - mn);
                s[i][j] = p;
                r += p;
            }
            rs[i] = r;
        }
#pragma unroll
        for (int off = 8; off > 0; off >>= 1)
#pragma unroll
            for (int i = 0; i < 4; i++)
                rs[i] += __shfl_xor_sync(0xffffffffu, rs[i], off);
#pragma unroll
        for (int i = 0; i < 4; i++) l_i[i] = l_i[i] * al[i] + rs[i];

        if (sx == 0) {
#pragma unroll
            for (int i = 0; i < 4; i++) alpha_sm[sr0 + i] = al[i];
        }
#pragma unroll
        for (int i = 0; i < 4; i++)
            *(float4*)&Psm[(sr0+i)*64 + sc0] =
                make_float4(s[i][0], s[i][1], s[i][2], s[i][3]);
        __syncthreads();

        // ---- O = alpha*O + P @ V (8x4 per thread; P reads are warp-broadcast)
        float av[8];
#pragma unroll
        for (int i = 0; i < 8; i++) av[i] = alpha_sm[or0 + i];
#pragma unroll
        for (int i = 0; i < 8; i++)
#pragma unroll
            for (int c = 0; c < 4; c++) oacc[i][c] *= av[i];

#pragma unroll 4
        for (int k = 0; k < 64; k += 4) {
            float4 v0 = *(const float4*)&Vs[(k+0)*128 + oc0];
            float4 v1 = *(const float4*)&Vs[(k+1)*128 + oc0];
            float4 v2 = *(const float4*)&Vs[(k+2)*128 + oc0];
            float4 v3 = *(const float4*)&Vs[(k+3)*128 + oc0];
#pragma unroll
            for (int i = 0; i < 8; i++) {
                float4 p = *(const float4*)&Psm[(or0+i)*64 + k];
                oacc[i][0] = fmaf(p.x,v0.x, fmaf(p.y,v1.x, fmaf(p.z,v2.x, fmaf(p.w,v3.x, oacc[i][0]))));
                oacc[i][1] = fmaf(p.x,v0.y, fmaf(p.y,v1.y, fmaf(p.z,v2.y, fmaf(p.w,v3.y, oacc[i][1]))));
                oacc[i][2] = fmaf(p.x,v0.z, fmaf(p.y,v1.z, fmaf(p.z,v2.z, fmaf(p.w,v3.z, oacc[i][2]))));
                oacc[i][3] = fmaf(p.x,v0.w, fmaf(p.y,v1.w, fmaf(p.z,v2.w, fmaf(p.w,v3.w, oacc[i][3]))));
            }
        }
    }

    if (sx == 0) {
#pragma unroll
        for (int i = 0; i < 4; i++) lsm[sr0 + i] = l_i[i];
    }
    __syncthreads();

    float* og = g_O + (long)(b*T_ + t0) * (H_*HD_) + h*HD_;
#pragma unroll
    for (int i = 0; i < 8; i++) {
        float inv = 1.0f / lsm[or0 + i];
        *(float4*)(og + (long)(or0+i)*(H_*HD_) + oc0) =
            make_float4(oacc[i][0]*inv, oacc[i][1]*inv, oacc[i][2]*inv, oacc[i][3]*inv);
    }
}

// =====================================================================
// host launcher
// =====================================================================
extern "C" void kernel_launch(void* const* d_in, const int* in_sizes, int n_in,
                              void* d_out, int out_size)
{
    const float* x  = (const float*)d_in[0];
    const float* wq = (const float*)d_in[1];
    const float* bq = (const float*)d_in[2];
    const float* wk = (const float*)d_in[3];
    const float* bk = (const float*)d_in[4];
    const float* wv = (const float*)d_in[5];
    const float* bv = (const float*)d_in[6];
    const float* wo = (const float*)d_in[7];
    float* out = (float*)d_out;

    float *qp, *kp, *vp, *op;
    cudaGetSymbolAddress((void**)&qp, g_Q);
    cudaGetSymbolAddress((void**)&kp, g_K);
    cudaGetSymbolAddress((void**)&vp, g_V);
    cudaGetSymbolAddress((void**)&op, g_O);

    dim3 blk(256);

    // QKV projections
    gemm_kernel<<<dim3(C_/128,      MROWS/128), blk>>>(x, wq, bq, qp, H_*HD_,   C_);
    gemm_kernel<<<dim3(KVH_*HD_/128, MROWS/128), blk>>>(x, wk, bk, kp, KVH_*HD_, C_);
    gemm_kernel<<<dim3(KVH_*HD_/128, MROWS/128), blk>>>(x, wv, bv, vp, KVH_*HD_, C_);

    // RoPE
    rope_q_kernel<<<(B_*T_*H_*64)/256, blk>>>();
    ropeT_k_kernel<<<dim3(T_/32, 2, B_*KVH_), blk>>>();

    // flash attention
    cudaFuncSetAttribute(flash_kernel,
                         cudaFuncAttributeMaxDynamicSharedMemorySize, 115200);
    flash_kernel<<<dim3(T_/64, H_, B_), blk, 115200>>>();

    // output projection
    gemm_kernel<<<dim3(C_/128, MROWS/128), blk>>>(op, wo, nullptr, out, C_, H_*HD_*C_/C_ == 0 ? C_ : H_*HD_);
}

// round 5
// speedup vs baseline: 1.5624x; 1.5624x over previous
#include <cuda_runtime.h>
#include <math.h>
#include <stdint.h>

#define B_   2
#define T_   2048
#define C_   2048
#define H_   16
#define KVH_ 4
#define HD_  128
#define MROWS (B_*T_)   // 4096

// ---------------- scratch (device globals; no allocations) ----------------
__device__ float g_Q[B_*T_*H_*HD_];       // [b*T+t][h*128+d]
__device__ float g_K[B_*T_*KVH_*HD_];     // [b*T+s][kh*128+d]
__device__ float g_V[B_*T_*KVH_*HD_];
__device__ float g_Kt[B_*KVH_*HD_*T_];    // [((b*KVH+kh)*128+d)*T + s]
__device__ float g_O[B_*T_*H_*HD_];

// ==================== mma.sync tf32 helpers (arch-agnostic) ====================
__device__ __forceinline__ uint32_t f2tf(float f) {
    uint32_t r;
    asm("cvt.rna.tf32.f32 %0, %1;" : "=r"(r) : "f"(f));
    return r;
}

__device__ __forceinline__ void mma_tf32(float* c, const uint32_t* a, const uint32_t* b) {
    asm volatile(
        "mma.sync.aligned.m16n8k8.row.col.f32.tf32.tf32.f32 "
        "{%0,%1,%2,%3}, {%4,%5,%6,%7}, {%8,%9}, {%0,%1,%2,%3};"
        : "+f"(c[0]), "+f"(c[1]), "+f"(c[2]), "+f"(c[3])
        : "r"(a[0]), "r"(a[1]), "r"(a[2]), "r"(a[3]), "r"(b[0]), "r"(b[1]));
}

// =====================================================================
// Tensor-core tf32 GEMM:  C[M,N] = A[M,K] @ W[K,N] (+bias)
// 128x128 CTA tile, BK=16, 256 threads (8 warps, 2x4), warp tile 64x32.
// =====================================================================
#define ASTRIDE 20
#define BSTRIDE 132

__global__ void __launch_bounds__(256) gemm_mma(
    const float* __restrict__ A, const float* __restrict__ W,
    const float* __restrict__ bias, float* __restrict__ Cout,
    int N, int K)
{
    __shared__ uint32_t As[2][128 * ASTRIDE];   // [m][k] tf32
    __shared__ uint32_t Bs[2][16 * BSTRIDE];    // [k][n] tf32

    const int tid  = threadIdx.x;
    const int wid  = tid >> 5;
    const int lane = tid & 31;
    const int g    = lane >> 2;    // groupID
    const int tg   = lane & 3;     // threadID_in_group
    const int rowBlk = blockIdx.y * 128;
    const int colBlk = blockIdx.x * 128;
    const int warp_m = (wid & 1) * 64;
    const int warp_n = (wid >> 1) * 32;

    float acc[4][4][4];
#pragma unroll
    for (int mt = 0; mt < 4; mt++)
#pragma unroll
        for (int nt = 0; nt < 4; nt++)
#pragma unroll
            for (int i = 0; i < 4; i++) acc[mt][nt][i] = 0.f;

    // loader mapping
    const int ar  = tid >> 1;           // A row 0..127
    const int akc = (tid & 1) * 8;      // A col base (two float4)
    const int bk  = tid >> 4;           // B k-row 0..15
    const int bn  = (tid & 15) * 8;     // B col base (two float4)

    const float* Ag = A + (long)(rowBlk + ar) * K + akc;
    const float* Wg = W + (long)bk * N + colBlk + bn;

    const int nit = K / 16;

    // ---- load tile 0 directly ----
    {
        float4 a0 = *(const float4*)(Ag);
        float4 a1 = *(const float4*)(Ag + 4);
        float4 b0 = *(const float4*)(Wg);
        float4 b1 = *(const float4*)(Wg + 4);
        uint32_t* ap = &As[0][ar * ASTRIDE + akc];
        ap[0]=f2tf(a0.x); ap[1]=f2tf(a0.y); ap[2]=f2tf(a0.z); ap[3]=f2tf(a0.w);
        ap[4]=f2tf(a1.x); ap[5]=f2tf(a1.y); ap[6]=f2tf(a1.z); ap[7]=f2tf(a1.w);
        uint32_t* bp = &Bs[0][bk * BSTRIDE + bn];
        bp[0]=f2tf(b0.x); bp[1]=f2tf(b0.y); bp[2]=f2tf(b0.z); bp[3]=f2tf(b0.w);
        bp[4]=f2tf(b1.x); bp[5]=f2tf(b1.y); bp[6]=f2tf(b1.z); bp[7]=f2tf(b1.w);
    }
    __syncthreads();

    for (int it = 0; it < nit; it++) {
        const int cur = it & 1;
        float4 pa0, pa1, pb0, pb1;
        if (it + 1 < nit) {
            const float* Agn = Ag + (it + 1) * 16;
            const float* Wgn = Wg + (long)(it + 1) * 16 * N;
            pa0 = *(const float4*)(Agn);
            pa1 = *(const float4*)(Agn + 4);
            pb0 = *(const float4*)(Wgn);
            pb1 = *(const float4*)(Wgn + 4);
        }

        // ---- compute on buffer cur ----
#pragma unroll
        for (int ks = 0; ks < 16; ks += 8) {
            uint32_t afr[4][4], bfr[4][2];
#pragma unroll
            for (int mt = 0; mt < 4; mt++) {
                int arow = warp_m + mt * 16 + g;
                int acol = ks + tg;
                afr[mt][0] = As[cur][arow * ASTRIDE + acol];
                afr[mt][1] = As[cur][(arow + 8) * ASTRIDE + acol];
                afr[mt][2] = As[cur][arow * ASTRIDE + acol + 4];
                afr[mt][3] = As[cur][(arow + 8) * ASTRIDE + acol + 4];
            }
#pragma unroll
            for (int nt = 0; nt < 4; nt++) {
                int brow = ks + tg;
                int bcol = warp_n + nt * 8 + g;
                bfr[nt][0] = Bs[cur][brow * BSTRIDE + bcol];
                bfr[nt][1] = Bs[cur][(brow + 4) * BSTRIDE + bcol];
            }
#pragma unroll
            for (int mt = 0; mt < 4; mt++)
#pragma unroll
                for (int nt = 0; nt < 4; nt++)
                    mma_tf32(acc[mt][nt], afr[mt], bfr[nt]);
        }
        __syncthreads();

        if (it + 1 < nit) {
            const int nxt = cur ^ 1;
            uint32_t* ap = &As[nxt][ar * ASTRIDE + akc];
            ap[0]=f2tf(pa0.x); ap[1]=f2tf(pa0.y); ap[2]=f2tf(pa0.z); ap[3]=f2tf(pa0.w);
            ap[4]=f2tf(pa1.x); ap[5]=f2tf(pa1.y); ap[6]=f2tf(pa1.z); ap[7]=f2tf(pa1.w);
            uint32_t* bp = &Bs[nxt][bk * BSTRIDE + bn];
            bp[0]=f2tf(pb0.x); bp[1]=f2tf(pb0.y); bp[2]=f2tf(pb0.z); bp[3]=f2tf(pb0.w);
            bp[4]=f2tf(pb1.x); bp[5]=f2tf(pb1.y); bp[6]=f2tf(pb1.z); bp[7]=f2tf(pb1.w);
            __syncthreads();
        }
    }

    // ---- epilogue ----
#pragma unroll
    for (int mt = 0; mt < 4; mt++) {
        int row = rowBlk + warp_m + mt * 16 + g;
#pragma unroll
        for (int nt = 0; nt < 4; nt++) {
            int col = colBlk + warp_n + nt * 8 + 2 * tg;
            float b0 = 0.f, b1 = 0.f;
            if (bias) { b0 = bias[col]; b1 = bias[col + 1]; }
            float* c0 = Cout + (long)row * N + col;
            float* c1 = Cout + (long)(row + 8) * N + col;
            *(float2*)c0 = make_float2(acc[mt][nt][0] + b0, acc[mt][nt][1] + b1);
            *(float2*)c1 = make_float2(acc[mt][nt][2] + b0, acc[mt][nt][3] + b1);
        }
    }
}

// =====================================================================
// RoPE on Q, in place.
// =====================================================================
__global__ void __launch_bounds__(256) rope_q_kernel()
{
    int idx = blockIdx.x * 256 + threadIdx.x;   // over B*T*H*64
    int d  = idx & 63;
    int rh = idx >> 6;
    int h  = rh & (H_ - 1);
    int bt = rh >> 4;
    int t  = bt & (T_ - 1);
    long base = (long)bt * (H_*HD_) + h * HD_;
    float invf = expf(-(float)d * (9.210340371976184f / 64.0f));
    float sn, cs;
    sincosf((float)t * invf, &sn, &cs);
    float x1 = g_Q[base + d];
    float x2 = g_Q[base + d + 64];
    g_Q[base + d]      = x1 * cs - x2 * sn;
    g_Q[base + d + 64] = x2 * cs + x1 * sn;
}

// =====================================================================
// RoPE on K + transpose to [B,KVH,HD,T].
// =====================================================================
__global__ void __launch_bounds__(256) ropeT_k_kernel()
{
    __shared__ float sm1[32][33];
    __shared__ float sm2[32][33];
    const int tid = threadIdx.x;
    const int s0  = blockIdx.x * 32;
    const int d0  = blockIdx.y * 32;
    const int bkh = blockIdx.z;
    const int b   = bkh >> 2;
    const int kh  = bkh & 3;

    {
        int r  = tid >> 3;
        int c4 = (tid & 7) * 4;
        long gbase = (long)(b*T_ + s0 + r) * (KVH_*HD_) + kh * HD_;
        float4 v1 = *(const float4*)(g_K + gbase + d0 + c4);
        float4 v2 = *(const float4*)(g_K + gbase + d0 + 64 + c4);
        sm1[r][c4+0]=v1.x; sm1[r][c4+1]=v1.y; sm1[r][c4+2]=v1.z; sm1[r][c4+3]=v1.w;
        sm2[r][c4+0]=v2.x; sm2[r][c4+1]=v2.y; sm2[r][c4+2]=v2.z; sm2[r][c4+3]=v2.w;
    }
    __syncthreads();

    const int dl = tid >> 2;
    const int cg = tid & 3;
    const int dd = dl & 31;
    float invf = expf(-(float)(d0 + dd) * (9.210340371976184f / 64.0f));
    int dglob = (dl < 32) ? (d0 + dd) : (64 + d0 + dd);
    long obase = (long)(bkh * HD_ + dglob) * T_;
#pragma unroll
    for (int i = 0; i < 8; i++) {
        int cc = cg * 8 + i;
        int t  = s0 + cc;
        float sn, cs;
        sincosf((float)t * invf, &sn, &cs);
        float x1 = sm1[cc][dd];
        float x2 = sm2[cc][dd];
        float out = (dl < 32) ? (x1 * cs - x2 * sn) : (x2 * cs + x1 * sn);
        g_Kt[obase + t] = out;
    }
}

// =====================================================================
// Flash attention (causal, GQA), fp32 SIMT. BM=BN=64, 256 threads.
// =====================================================================
__global__ void __launch_bounds__(256, 2) flash_kernel()
{
    extern __shared__ float sm[];
    float* Qs       = sm;                  // [64][128]
    float* Kts      = Qs  + 64*128;        // [128][64]
    float* Vs       = Kts + 128*64;        // [64][128]
    float* Psm      = Vs  + 64*128;        // [64][64]
    float* alpha_sm = Psm + 64*64;         // [64]
    float* lsm      = alpha_sm + 64;       // [64]

    const int tid = threadIdx.x;
    const int qt  = blockIdx.x;
    const int h   = blockIdx.y;
    const int b   = blockIdx.z;
    const int kh  = h >> 2;
    const int t0  = qt * 64;

    {
        const float* qg = g_Q + (long)(b*T_ + t0) * (H_*HD_) + h*HD_;
#pragma unroll
        for (int it = 0; it < 8; it++) {
            int idx = tid + it*256;
            int r = idx >> 5, d4 = (idx & 31) * 4;
            *(float4*)&Qs[r*128 + d4] = *(const float4*)(qg + (long)r*(H_*HD_) + d4);
        }
    }

    const int sx = tid & 15, sy = tid >> 4;
    const int sr0 = sy*4,  sc0 = sx*4;
    const int ocx = tid & 31, ory = tid >> 5;
    const int or0 = ory*8, oc0 = ocx*4;

    float m_i[4], l_i[4];
#pragma unroll
    for (int i = 0; i < 4; i++) { m_i[i] = -1e30f; l_i[i] = 0.f; }
    float oacc[8][4];
#pragma unroll
    for (int i = 0; i < 8; i++)
#pragma unroll
        for (int c = 0; c < 4; c++) oacc[i][c] = 0.f;

    const float* kg = g_Kt + (long)(b*KVH_ + kh) * HD_ * T_;
    const float* vg = g_V  + (long)b*T_*(KVH_*HD_) + kh*HD_;
    const float scale = 0.08838834764831845f;

    for (int kt = 0; kt <= qt; kt++) {
        const int s0 = kt * 64;
        __syncthreads();
#pragma unroll
        for (int it = 0; it < 8; it++) {
            int idx = tid + it*256;
            int d = idx >> 4, c4 = (idx & 15) * 4;
            *(float4*)&Kts[d*64 + c4] = *(const float4*)(kg + (long)d*T_ + s0 + c4);
        }
#pragma unroll
        for (int it = 0; it < 8; it++) {
            int idx = tid + it*256;
            int c = idx >> 5, d4 = (idx & 31) * 4;
            *(float4*)&Vs[c*128 + d4] = *(const float4*)(vg + (long)(s0 + c)*(KVH_*HD_) + d4);
        }
        __syncthreads();

        float s[4][4];
#pragma unroll
        for (int i = 0; i < 4; i++)
#pragma unroll
            for (int j = 0; j < 4; j++) s[i][j] = 0.f;

#pragma unroll 4
        for (int dq = 0; dq < 128; dq += 4) {
            float4 q0 = *(const float4*)&Qs[(sr0+0)*128 + dq];
            float4 q1 = *(const float4*)&Qs[(sr0+1)*128 + dq];
            float4 q2 = *(const float4*)&Qs[(sr0+2)*128 + dq];
            float4 q3 = *(const float4*)&Qs[(sr0+3)*128 + dq];
            float4 k0 = *(const float4*)&Kts[(dq+0)*64 + sc0];
            float4 k1 = *(const float4*)&Kts[(dq+1)*64 + sc0];
            float4 k2 = *(const float4*)&Kts[(dq+2)*64 + sc0];
            float4 k3 = *(const float4*)&Kts[(dq+3)*64 + sc0];
#define SROW(i, qv) \
            s[i][0] = fmaf(qv.x,k0.x, fmaf(qv.y,k1.x, fmaf(qv.z,k2.x, fmaf(qv.w,k3.x, s[i][0])))); \
            s[i][1] = fmaf(qv.x,k0.y, fmaf(qv.y,k1.y, fmaf(qv.z,k2.y, fmaf(qv.w,k3.y, s[i][1])))); \
            s[i][2] = fmaf(qv.x,k0.z, fmaf(qv.y,k1.z, fmaf(qv.z,k2.z, fmaf(qv.w,k3.z, s[i][2])))); \
            s[i][3] = fmaf(qv.x,k0.w, fmaf(qv.y,k1.w, fmaf(qv.z,k2.w, fmaf(qv.w,k3.w, s[i][3]))));
            SROW(0, q0) SROW(1, q1) SROW(2, q2) SROW(3, q3)
#undef SROW
        }

        if (kt == qt) {
#pragma unroll
            for (int i = 0; i < 4; i++)
#pragma unroll
                for (int j = 0; j < 4; j++) {
                    s[i][j] *= scale;
                    if (s0 + sc0 + j > t0 + sr0 + i) s[i][j] = -1e30f;
                }
        } else {
#pragma unroll
            for (int i = 0; i < 4; i++)
#pragma unroll
                for (int j = 0; j < 4; j++) s[i][j] *= scale;
        }

        float mt[4];
#pragma unroll
        for (int i = 0; i < 4; i++)
            mt[i] = fmaxf(fmaxf(s[i][0], s[i][1]), fmaxf(s[i][2], s[i][3]));
#pragma unroll
        for (int off = 8; off > 0; off >>= 1)
#pragma unroll
            for (int i = 0; i < 4; i++)
                mt[i] = fmaxf(mt[i], __shfl_xor_sync(0xffffffffu, mt[i], off));

        float al[4], rs[4];
#pragma unroll
        for (int i = 0; i < 4; i++) {
            float mn = fmaxf(m_i[i], mt[i]);
            al[i] = __expf(m_i[i] - mn);
            m_i[i] = mn;
            float r = 0.f;
#pragma unroll
            for (int j = 0; j < 4; j++) {
                float p = __expf(s[i][j] - mn);
                s[i][j] = p;
                r += p;
            }
            rs[i] = r;
        }
#pragma unroll
        for (int off = 8; off > 0; off >>= 1)
#pragma unroll
            for (int i = 0; i < 4; i++)
                rs[i] += __shfl_xor_sync(0xffffffffu, rs[i], off);
#pragma unroll
        for (int i = 0; i < 4; i++) l_i[i] = l_i[i] * al[i] + rs[i];

        if (sx == 0) {
#pragma unroll
            for (int i = 0; i < 4; i++) alpha_sm[sr0 + i] = al[i];
        }
#pragma unroll
        for (int i = 0; i < 4; i++)
            *(float4*)&Psm[(sr0+i)*64 + sc0] =
                make_float4(s[i][0], s[i][1], s[i][2], s[i][3]);
        __syncthreads();

        float av[8];
#pragma unroll
        for (int i = 0; i < 8; i++) av[i] = alpha_sm[or0 + i];
#pragma unroll
        for (int i = 0; i < 8; i++)
#pragma unroll
            for (int c = 0; c < 4; c++) oacc[i][c] *= av[i];

#pragma unroll 4
        for (int k = 0; k < 64; k += 4) {
            float4 v0 = *(const float4*)&Vs[(k+0)*128 + oc0];
            float4 v1 = *(const float4*)&Vs[(k+1)*128 + oc0];
            float4 v2 = *(const float4*)&Vs[(k+2)*128 + oc0];
            float4 v3 = *(const float4*)&Vs[(k+3)*128 + oc0];
#pragma unroll
            for (int i = 0; i < 8; i++) {
                float4 p = *(const float4*)&Psm[(or0+i)*64 + k];
                oacc[i][0] = fmaf(p.x,v0.x, fmaf(p.y,v1.x, fmaf(p.z,v2.x, fmaf(p.w,v3.x, oacc[i][0]))));
                oacc[i][1] = fmaf(p.x,v0.y, fmaf(p.y,v1.y, fmaf(p.z,v2.y, fmaf(p.w,v3.y, oacc[i][1]))));
                oacc[i][2] = fmaf(p.x,v0.z, fmaf(p.y,v1.z, fmaf(p.z,v2.z, fmaf(p.w,v3.z, oacc[i][2]))));
                oacc[i][3] = fmaf(p.x,v0.w, fmaf(p.y,v1.w, fmaf(p.z,v2.w, fmaf(p.w,v3.w, oacc[i][3]))));
            }
        }
    }

    if (sx == 0) {
#pragma unroll
        for (int i = 0; i < 4; i++) lsm[sr0 + i] = l_i[i];
    }
    __syncthreads();

    float* og = g_O + (long)(b*T_ + t0) * (H_*HD_) + h*HD_;
#pragma unroll
    for (int i = 0; i < 8; i++) {
        float inv = 1.0f / lsm[or0 + i];
        *(float4*)(og + (long)(or0+i)*(H_*HD_) + oc0) =
            make_float4(oacc[i][0]*inv, oacc[i][1]*inv, oacc[i][2]*inv, oacc[i][3]*inv);
    }
}

// =====================================================================
// host launcher
// =====================================================================
extern "C" void kernel_launch(void* const* d_in, const int* in_sizes, int n_in,
                              void* d_out, int out_size)
{
    const float* x  = (const float*)d_in[0];
    const float* wq = (const float*)d_in[1];
    const float* bq = (const float*)d_in[2];
    const float* wk = (const float*)d_in[3];
    const float* bk = (const float*)d_in[4];
    const float* wv = (const float*)d_in[5];
    const float* bv = (const float*)d_in[6];
    const float* wo = (const float*)d_in[7];
    float* out = (float*)d_out;

    float *qp, *kp, *vp, *op;
    cudaGetSymbolAddress((void**)&qp, g_Q);
    cudaGetSymbolAddress((void**)&kp, g_K);
    cudaGetSymbolAddress((void**)&vp, g_V);
    cudaGetSymbolAddress((void**)&op, g_O);

    cudaFuncSetAttribute(flash_kernel,
                         cudaFuncAttributeMaxDynamicSharedMemorySize, 115200);

    dim3 blk(256);

    // QKV projections (tf32 mma.sync)
    gemm_mma<<<dim3((H_*HD_)/128,   MROWS/128), blk>>>(x, wq, bq, qp, H_*HD_,   C_);
    gemm_mma<<<dim3((KVH_*HD_)/128, MROWS/128), blk>>>(x, wk, bk, kp, KVH_*HD_, C_);
    gemm_mma<<<dim3((KVH_*HD_)/128, MROWS/128), blk>>>(x, wv, bv, vp, KVH_*HD_, C_);

    // RoPE
    rope_q_kernel<<<(B_*T_*H_*64)/256, blk>>>();
    ropeT_k_kernel<<<dim3(T_/32, 2, B_*KVH_), blk>>>();

    // flash attention (fp32 SIMT)
    flash_kernel<<<dim3(T_/64, H_, B_), blk, 115200>>>();

    // output projection (tf32 mma.sync)
    gemm_mma<<<dim3(C_/128, MROWS/128), blk>>>(op, wo, nullptr, out, C_, H_*HD_);
}

// round 6
// speedup vs baseline: 2.1353x; 1.3666x over previous
#include <cuda_runtime.h>
#include <math.h>
#include <stdint.h>

#define B_   2
#define T_   2048
#define C_   2048
#define H_   16
#define KVH_ 4
#define HD_  128
#define MROWS (B_*T_)   // 4096

// ---------------- scratch (device globals; no allocations) ----------------
__device__ float g_Q[B_*T_*H_*HD_];       // [b*T+t][h*128+d]
__device__ float g_K[B_*T_*KVH_*HD_];     // [b*T+s][kh*128+d]
__device__ float g_V[B_*T_*KVH_*HD_];
__device__ float g_Kt[B_*KVH_*HD_*T_];    // [((b*KVH+kh)*128+d)*T + s]
__device__ float g_O[B_*T_*H_*HD_];

// ==================== mma.sync tf32 helpers (arch-agnostic) ====================
__device__ __forceinline__ uint32_t smem_u32(const void* p) {
    uint32_t a;
    asm("{ .reg .u64 t; cvta.to.shared.u64 t, %1; cvt.u32.u64 %0, t; }"
        : "=r"(a) : "l"(p));
    return a;
}

__device__ __forceinline__ uint32_t f2tf(float f) {
    uint32_t r;
    asm("cvt.rna.tf32.f32 %0, %1;" : "=r"(r) : "f"(f));
    return r;
}

__device__ __forceinline__ void mma_tf32(float* c, const uint32_t* a, const uint32_t* b) {
    asm volatile(
        "mma.sync.aligned.m16n8k8.row.col.f32.tf32.tf32.f32 "
        "{%0,%1,%2,%3}, {%4,%5,%6,%7}, {%8,%9}, {%0,%1,%2,%3};"
        : "+f"(c[0]), "+f"(c[1]), "+f"(c[2]), "+f"(c[3])
        : "r"(a[0]), "r"(a[1]), "r"(a[2]), "r"(a[3]), "r"(b[0]), "r"(b[1]));
}

#define CPA16(dst, src) \
    asm volatile("cp.async.cg.shared.global [%0], [%1], 16;" \
                 :: "r"(dst), "l"(src) : "memory")
#define CP_COMMIT() asm volatile("cp.async.commit_group;" ::: "memory")
#define CP_WAIT1()  asm volatile("cp.async.wait_group 1;" ::: "memory")
#define CP_WAIT0()  asm volatile("cp.async.wait_group 0;" ::: "memory")

// =====================================================================
// Tensor-core tf32 GEMM:  C[M,N] = A[M,K] @ W[K,N] (+bias)   (unchanged R5)
// =====================================================================
#define ASTRIDE 20
#define BSTRIDE 132

__global__ void __launch_bounds__(256) gemm_mma(
    const float* __restrict__ A, const float* __restrict__ W,
    const float* __restrict__ bias, float* __restrict__ Cout,
    int N, int K)
{
    __shared__ uint32_t As[2][128 * ASTRIDE];   // [m][k] tf32
    __shared__ uint32_t Bs[2][16 * BSTRIDE];    // [k][n] tf32

    const int tid  = threadIdx.x;
    const int wid  = tid >> 5;
    const int lane = tid & 31;
    const int g    = lane >> 2;
    const int tg   = lane & 3;
    const int rowBlk = blockIdx.y * 128;
    const int colBlk = blockIdx.x * 128;
    const int warp_m = (wid & 1) * 64;
    const int warp_n = (wid >> 1) * 32;

    float acc[4][4][4];
#pragma unroll
    for (int mt = 0; mt < 4; mt++)
#pragma unroll
        for (int nt = 0; nt < 4; nt++)
#pragma unroll
            for (int i = 0; i < 4; i++) acc[mt][nt][i] = 0.f;

    const int ar  = tid >> 1;
    const int akc = (tid & 1) * 8;
    const int bk  = tid >> 4;
    const int bn  = (tid & 15) * 8;

    const float* Ag = A + (long)(rowBlk + ar) * K + akc;
    const float* Wg = W + (long)bk * N + colBlk + bn;

    const int nit = K / 16;

    {
        float4 a0 = *(const float4*)(Ag);
        float4 a1 = *(const float4*)(Ag + 4);
        float4 b0 = *(const float4*)(Wg);
        float4 b1 = *(const float4*)(Wg + 4);
        uint32_t* ap = &As[0][ar * ASTRIDE + akc];
        ap[0]=f2tf(a0.x); ap[1]=f2tf(a0.y); ap[2]=f2tf(a0.z); ap[3]=f2tf(a0.w);
        ap[4]=f2tf(a1.x); ap[5]=f2tf(a1.y); ap[6]=f2tf(a1.z); ap[7]=f2tf(a1.w);
        uint32_t* bp = &Bs[0][bk * BSTRIDE + bn];
        bp[0]=f2tf(b0.x); bp[1]=f2tf(b0.y); bp[2]=f2tf(b0.z); bp[3]=f2tf(b0.w);
        bp[4]=f2tf(b1.x); bp[5]=f2tf(b1.y); bp[6]=f2tf(b1.z); bp[7]=f2tf(b1.w);
    }
    __syncthreads();

    for (int it = 0; it < nit; it++) {
        const int cur = it & 1;
        float4 pa0, pa1, pb0, pb1;
        if (it + 1 < nit) {
            const float* Agn = Ag + (it + 1) * 16;
            const float* Wgn = Wg + (long)(it + 1) * 16 * N;
            pa0 = *(const float4*)(Agn);
            pa1 = *(const float4*)(Agn + 4);
            pb0 = *(const float4*)(Wgn);
            pb1 = *(const float4*)(Wgn + 4);
        }

#pragma unroll
        for (int ks = 0; ks < 16; ks += 8) {
            uint32_t afr[4][4], bfr[4][2];
#pragma unroll
            for (int mt = 0; mt < 4; mt++) {
                int arow = warp_m + mt * 16 + g;
                int acol = ks + tg;
                afr[mt][0] = As[cur][arow * ASTRIDE + acol];
                afr[mt][1] = As[cur][(arow + 8) * ASTRIDE + acol];
                afr[mt][2] = As[cur][arow * ASTRIDE + acol + 4];
                afr[mt][3] = As[cur][(arow + 8) * ASTRIDE + acol + 4];
            }
#pragma unroll
            for (int nt = 0; nt < 4; nt++) {
                int brow = ks + tg;
                int bcol = warp_n + nt * 8 + g;
                bfr[nt][0] = Bs[cur][brow * BSTRIDE + bcol];
                bfr[nt][1] = Bs[cur][(brow + 4) * BSTRIDE + bcol];
            }
#pragma unroll
            for (int mt = 0; mt < 4; mt++)
#pragma unroll
                for (int nt = 0; nt < 4; nt++)
                    mma_tf32(acc[mt][nt], afr[mt], bfr[nt]);
        }
        __syncthreads();

        if (it + 1 < nit) {
            const int nxt = cur ^ 1;
            uint32_t* ap = &As[nxt][ar * ASTRIDE + akc];
            ap[0]=f2tf(pa0.x); ap[1]=f2tf(pa0.y); ap[2]=f2tf(pa0.z); ap[3]=f2tf(pa0.w);
            ap[4]=f2tf(pa1.x); ap[5]=f2tf(pa1.y); ap[6]=f2tf(pa1.z); ap[7]=f2tf(pa1.w);
            uint32_t* bp = &Bs[nxt][bk * BSTRIDE + bn];
            bp[0]=f2tf(pb0.x); bp[1]=f2tf(pb0.y); bp[2]=f2tf(pb0.z); bp[3]=f2tf(pb0.w);
            bp[4]=f2tf(pb1.x); bp[5]=f2tf(pb1.y); bp[6]=f2tf(pb1.z); bp[7]=f2tf(pb1.w);
            __syncthreads();
        }
    }

#pragma unroll
    for (int mt = 0; mt < 4; mt++) {
        int row = rowBlk + warp_m + mt * 16 + g;
#pragma unroll
        for (int nt = 0; nt < 4; nt++) {
            int col = colBlk + warp_n + nt * 8 + 2 * tg;
            float b0 = 0.f, b1 = 0.f;
            if (bias) { b0 = bias[col]; b1 = bias[col + 1]; }
            float* c0 = Cout + (long)row * N + col;
            float* c1 = Cout + (long)(row + 8) * N + col;
            *(float2*)c0 = make_float2(acc[mt][nt][0] + b0, acc[mt][nt][1] + b1);
            *(float2*)c1 = make_float2(acc[mt][nt][2] + b0, acc[mt][nt][3] + b1);
        }
    }
}

// =====================================================================
// RoPE on Q, in place.
// =====================================================================
__global__ void __launch_bounds__(256) rope_q_kernel()
{
    int idx = blockIdx.x * 256 + threadIdx.x;
    int d  = idx & 63;
    int rh = idx >> 6;
    int h  = rh & (H_ - 1);
    int bt = rh >> 4;
    int t  = bt & (T_ - 1);
    long base = (long)bt * (H_*HD_) + h * HD_;
    float invf = expf(-(float)d * (9.210340371976184f / 64.0f));
    float sn, cs;
    sincosf((float)t * invf, &sn, &cs);
    float x1 = g_Q[base + d];
    float x2 = g_Q[base + d + 64];
    g_Q[base + d]      = x1 * cs - x2 * sn;
    g_Q[base + d + 64] = x2 * cs + x1 * sn;
}

// =====================================================================
// RoPE on K + transpose to [B,KVH,HD,T].
// =====================================================================
__global__ void __launch_bounds__(256) ropeT_k_kernel()
{
    __shared__ float sm1[32][33];
    __shared__ float sm2[32][33];
    const int tid = threadIdx.x;
    const int s0  = blockIdx.x * 32;
    const int d0  = blockIdx.y * 32;
    const int bkh = blockIdx.z;
    const int b   = bkh >> 2;
    const int kh  = bkh & 3;

    {
        int r  = tid >> 3;
        int c4 = (tid & 7) * 4;
        long gbase = (long)(b*T_ + s0 + r) * (KVH_*HD_) + kh * HD_;
        float4 v1 = *(const float4*)(g_K + gbase + d0 + c4);
        float4 v2 = *(const float4*)(g_K + gbase + d0 + 64 + c4);
        sm1[r][c4+0]=v1.x; sm1[r][c4+1]=v1.y; sm1[r][c4+2]=v1.z; sm1[r][c4+3]=v1.w;
        sm2[r][c4+0]=v2.x; sm2[r][c4+1]=v2.y; sm2[r][c4+2]=v2.z; sm2[r][c4+3]=v2.w;
    }
    __syncthreads();

    const int dl = tid >> 2;
    const int cg = tid & 3;
    const int dd = dl & 31;
    float invf = expf(-(float)(d0 + dd) * (9.210340371976184f / 64.0f));
    int dglob = (dl < 32) ? (d0 + dd) : (64 + d0 + dd);
    long obase = (long)(bkh * HD_ + dglob) * T_;
#pragma unroll
    for (int i = 0; i < 8; i++) {
        int cc = cg * 8 + i;
        int t  = s0 + cc;
        float sn, cs;
        sincosf((float)t * invf, &sn, &cs);
        float x1 = sm1[cc][dd];
        float x2 = sm2[cc][dd];
        float out = (dl < 32) ? (x1 * cs - x2 * sn) : (x2 * cs + x1 * sn);
        g_Kt[obase + t] = out;
    }
}

// =====================================================================
// Tensor-core flash attention (causal, GQA).
// BM=128, BN=64, 256 threads (8 warps x 16 rows). tf32 mma for S and PV.
// K/V tiles streamed via cp.async (raw fp32 -> HW tf32 truncation).
// smem: Qs[128][132]u32 | Kt[2][128][68]u32 | Vs[2][64][132]u32 = 204800 B
// =====================================================================
#define FQS 132
#define FKS 68
#define FVS 132
#define KOFF 67584                 // 128*132*4
#define KSZ  34816                 // 128*68*4
#define VOFF (KOFF + 2*KSZ)        // 137216
#define VSZ  33792                 // 64*132*4
#define FLASH_SMEM (VOFF + 2*VSZ)  // 204800

__global__ void __launch_bounds__(256) flash_tc()
{
    extern __shared__ char smem[];
    uint32_t* Qs  = (uint32_t*)smem;
    const uint32_t sb = smem_u32(smem);

    const int tid = threadIdx.x;
    const int qt  = blockIdx.x;
    const int h   = blockIdx.y;
    const int b   = blockIdx.z;
    const int kh  = h >> 2;
    const int t0  = qt * 128;
    const int wm  = (tid >> 5) * 16;
    const int lane = tid & 31;
    const int g = lane >> 2, tg = lane & 3;

    const float* kg = g_Kt + (long)(b*KVH_ + kh) * HD_ * T_;   // [d][s]
    const float* vg = g_V  + (long)b*T_*(KVH_*HD_) + kh*HD_;   // [s][d]
    const float scale = 0.08838834764831845f;                  // 1/sqrt(128)

    // ---- Q tile: LDG -> scale -> tf32(round) -> smem ----
    {
        const float* qg = g_Q + (long)(b*T_ + t0) * (H_*HD_) + h*HD_;
#pragma unroll
        for (int it = 0; it < 16; it++) {
            int idx = tid + it*256;
            int r = idx >> 5, d4 = (idx & 31) * 4;
            float4 v = *(const float4*)(qg + (long)r*(H_*HD_) + d4);
            uint32_t* qp = &Qs[r*FQS + d4];
            qp[0] = f2tf(v.x * scale); qp[1] = f2tf(v.y * scale);
            qp[2] = f2tf(v.z * scale); qp[3] = f2tf(v.w * scale);
        }
    }

    const int nkt = 2*qt + 2;

    // ---- prologue: cp.async tile 0 into buffer 0 ----
    {
        const int s0n = 0;
#pragma unroll
        for (int it = 0; it < 8; it++) {
            int idx = tid + it*256;
            int d = idx >> 4, c4 = (idx & 15) * 4;
            CPA16(sb + KOFF + (d*FKS + c4)*4, (const void*)(kg + (long)d*T_ + s0n + c4));
        }
#pragma unroll
        for (int it = 0; it < 8; it++) {
            int idx = tid + it*256;
            int c = idx >> 5, d4 = (idx & 31) * 4;
            CPA16(sb + VOFF + (c*FVS + d4)*4, (const void*)(vg + (long)(s0n + c)*(KVH_*HD_) + d4));
        }
        CP_COMMIT();
    }

    float o[16][4];
#pragma unroll
    for (int nt = 0; nt < 16; nt++)
#pragma unroll
        for (int i = 0; i < 4; i++) o[nt][i] = 0.f;
    float m0 = -1e30f, m1 = -1e30f, l0 = 0.f, l1 = 0.f;

    for (int kt = 0; kt < nkt; kt++) {
        const int cur = kt & 1;
        if (kt + 1 < nkt) {
            const int s0n = (kt + 1) * 64;
            const int sel = cur ^ 1;
#pragma unroll
            for (int it = 0; it < 8; it++) {
                int idx = tid + it*256;
                int d = idx >> 4, c4 = (idx & 15) * 4;
                CPA16(sb + KOFF + sel*KSZ + (d*FKS + c4)*4,
                      (const void*)(kg + (long)d*T_ + s0n + c4));
            }
#pragma unroll
            for (int it = 0; it < 8; it++) {
                int idx = tid + it*256;
                int c = idx >> 5, d4 = (idx & 31) * 4;
                CPA16(sb + VOFF + sel*VSZ + (c*FVS + d4)*4,
                      (const void*)(vg + (long)(s0n + c)*(KVH_*HD_) + d4));
            }
            CP_COMMIT();
            CP_WAIT1();
        } else {
            CP_WAIT0();
        }
        __syncthreads();

        const uint32_t* Kc = (const uint32_t*)(smem + KOFF + cur*KSZ);
        const uint32_t* Vc = (const uint32_t*)(smem + VOFF + cur*VSZ);

        // ---- S = Q @ K^T (scaled; tf32 mma) ----
        float sf[8][4];
#pragma unroll
        for (int nt = 0; nt < 8; nt++)
#pragma unroll
            for (int i = 0; i < 4; i++) sf[nt][i] = 0.f;

#pragma unroll
        for (int kd = 0; kd < 16; kd++) {
            uint32_t a[4];
            a[0] = Qs[(wm+g)*FQS   + kd*8 + tg];
            a[1] = Qs[(wm+g+8)*FQS + kd*8 + tg];
            a[2] = Qs[(wm+g)*FQS   + kd*8 + tg + 4];
            a[3] = Qs[(wm+g+8)*FQS + kd*8 + tg + 4];
#pragma unroll
            for (int nt = 0; nt < 8; nt++) {
                uint32_t bb[2];
                bb[0] = Kc[(kd*8+tg)*FKS   + nt*8 + g];
                bb[1] = Kc[(kd*8+tg+4)*FKS + nt*8 + g];
                mma_tf32(sf[nt], a, bb);
            }
        }

        // ---- causal mask (only the two diagonal tiles) ----
        if (kt >= nkt - 2) {
            const int s0c = kt * 64;
            const int r0 = t0 + wm + g, r1 = r0 + 8;
#pragma unroll
            for (int nt = 0; nt < 8; nt++) {
                int c0 = s0c + nt*8 + 2*tg;
                if (c0     > r0) sf[nt][0] = -1e30f;
                if (c0 + 1 > r0) sf[nt][1] = -1e30f;
                if (c0     > r1) sf[nt][2] = -1e30f;
                if (c0 + 1 > r1) sf[nt][3] = -1e30f;
            }
        }

        // ---- online softmax (all in registers; rows g and g+8) ----
        float mt0 = -1e30f, mt1 = -1e30f;
#pragma unroll
        for (int nt = 0; nt < 8; nt++) {
            mt0 = fmaxf(mt0, fmaxf(sf[nt][0], sf[nt][1]));
            mt1 = fmaxf(mt1, fmaxf(sf[nt][2], sf[nt][3]));
        }
        mt0 = fmaxf(mt0, __shfl_xor_sync(0xffffffffu, mt0, 1));
        mt0 = fmaxf(mt0, __shfl_xor_sync(0xffffffffu, mt0, 2));
        mt1 = fmaxf(mt1, __shfl_xor_sync(0xffffffffu, mt1, 1));
        mt1 = fmaxf(mt1, __shfl_xor_sync(0xffffffffu, mt1, 2));

        float mn0 = fmaxf(m0, mt0), mn1 = fmaxf(m1, mt1);
        float al0 = __expf(m0 - mn0), al1 = __expf(m1 - mn1);
        m0 = mn0; m1 = mn1;

        float rs0 = 0.f, rs1 = 0.f;
        uint32_t pf[8][4];
#pragma unroll
        for (int nt = 0; nt < 8; nt++) {
            float p0 = __expf(sf[nt][0] - mn0);
            float p1 = __expf(sf[nt][1] - mn0);
            float p2 = __expf(sf[nt][2] - mn1);
            float p3 = __expf(sf[nt][3] - mn1);
            rs0 += p0 + p1; rs1 += p2 + p3;
            pf[nt][0] = f2tf(p0); pf[nt][1] = f2tf(p1);
            pf[nt][2] = f2tf(p2); pf[nt][3] = f2tf(p3);
        }
        rs0 += __shfl_xor_sync(0xffffffffu, rs0, 1);
        rs0 += __shfl_xor_sync(0xffffffffu, rs0, 2);
        rs1 += __shfl_xor_sync(0xffffffffu, rs1, 1);
        rs1 += __shfl_xor_sync(0xffffffffu, rs1, 2);
        l0 = l0 * al0 + rs0;
        l1 = l1 * al1 + rs1;

#pragma unroll
        for (int nt = 0; nt < 16; nt++) {
            o[nt][0] *= al0; o[nt][1] *= al0;
            o[nt][2] *= al1; o[nt][3] *= al1;
        }

        // ---- O += P @ V (A-fragments from pf via intra-warp shuffles) ----
#pragma unroll
        for (int ks = 0; ks < 8; ks++) {
            const int src1 = (g << 2) | (tg >> 1);
            uint32_t u0 = __shfl_sync(0xffffffffu, pf[ks][0], src1);
            uint32_t u1 = __shfl_sync(0xffffffffu, pf[ks][1], src1);
            uint32_t u2 = __shfl_sync(0xffffffffu, pf[ks][2], src1);
            uint32_t u3 = __shfl_sync(0xffffffffu, pf[ks][3], src1);
            uint32_t w0 = __shfl_sync(0xffffffffu, pf[ks][0], src1 + 2);
            uint32_t w1 = __shfl_sync(0xffffffffu, pf[ks][1], src1 + 2);
            uint32_t w2 = __shfl_sync(0xffffffffu, pf[ks][2], src1 + 2);
            uint32_t w3 = __shfl_sync(0xffffffffu, pf[ks][3], src1 + 2);
            uint32_t a[4];
            a[0] = (tg & 1) ? u1 : u0;
            a[1] = (tg & 1) ? u3 : u2;
            a[2] = (tg & 1) ? w1 : w0;
            a[3] = (tg & 1) ? w3 : w2;
#pragma unroll
            for (int nt = 0; nt < 16; nt++) {
                uint32_t bb[2];
                bb[0] = Vc[(ks*8+tg)*FVS   + nt*8 + g];
                bb[1] = Vc[(ks*8+tg+4)*FVS + nt*8 + g];
                mma_tf32(o[nt], a, bb);
            }
        }
        __syncthreads();
    }

    // ---- epilogue: normalize and store ----
    const float inv0 = 1.0f / l0, inv1 = 1.0f / l1;
    float* og0 = g_O + (long)(b*T_ + t0 + wm + g) * (H_*HD_) + h*HD_;
    float* og1 = og0 + 8L * (H_*HD_);
#pragma unroll
    for (int nt = 0; nt < 16; nt++) {
        int c = nt*8 + 2*tg;
        *(float2*)(og0 + c) = make_float2(o[nt][0]*inv0, o[nt][1]*inv0);
        *(float2*)(og1 + c) = make_float2(o[nt][2]*inv1, o[nt][3]*inv1);
    }
}

// =====================================================================
// host launcher
// =====================================================================
extern "C" void kernel_launch(void* const* d_in, const int* in_sizes, int n_in,
                              void* d_out, int out_size)
{
    const float* x  = (const float*)d_in[0];
    const float* wq = (const float*)d_in[1];
    const float* bq = (const float*)d_in[2];
    const float* wk = (const float*)d_in[3];
    const float* bk = (const float*)d_in[4];
    const float* wv = (const float*)d_in[5];
    const float* bv = (const float*)d_in[6];
    const float* wo = (const float*)d_in[7];
    float* out = (float*)d_out;

    float *qp, *kp, *vp, *op;
    cudaGetSymbolAddress((void**)&qp, g_Q);
    cudaGetSymbolAddress((void**)&kp, g_K);
    cudaGetSymbolAddress((void**)&vp, g_V);
    cudaGetSymbolAddress((void**)&op, g_O);

    cudaFuncSetAttribute(flash_tc,
                         cudaFuncAttributeMaxDynamicSharedMemorySize, FLASH_SMEM);

    dim3 blk(256);

    // QKV projections (tf32 mma.sync)
    gemm_mma<<<dim3((H_*HD_)/128,   MROWS/128), blk>>>(x, wq, bq, qp, H_*HD_,   C_);
    gemm_mma<<<dim3((KVH_*HD_)/128, MROWS/128), blk>>>(x, wk, bk, kp, KVH_*HD_, C_);
    gemm_mma<<<dim3((KVH_*HD_)/128, MROWS/128), blk>>>(x, wv, bv, vp, KVH_*HD_, C_);

    // RoPE
    rope_q_kernel<<<(B_*T_*H_*64)/256, blk>>>();
    ropeT_k_kernel<<<dim3(T_/32, 2, B_*KVH_), blk>>>();

    // tensor-core flash attention
    flash_tc<<<dim3(T_/128, H_, B_), blk, FLASH_SMEM>>>();

    // output projection (tf32 mma.sync)
    gemm_mma<<<dim3(C_/128, MROWS/128), blk>>>(op, wo, nullptr, out, C_, H_*HD_);
}